// round 10
// baseline (speedup 1.0000x reference)
#include <cuda_runtime.h>

typedef unsigned long long ull;

// ---------------- packed f32x2 helpers (Blackwell FFMA2 path) ----------------
__device__ __forceinline__ ull pack2(float a, float b) {
    ull r; asm("mov.b64 %0, {%1,%2};" : "=l"(r) : "f"(a), "f"(b)); return r;
}
__device__ __forceinline__ float2 unpack2(ull v) {
    float2 f; asm("mov.b64 {%0,%1}, %2;" : "=f"(f.x), "=f"(f.y) : "l"(v)); return f;
}
__device__ __forceinline__ ull ffma2(ull a, ull b, ull c) {
    ull d; asm("fma.rn.f32x2 %0, %1, %2, %3;" : "=l"(d) : "l"(a), "l"(b), "l"(c)); return d;
}
__device__ __forceinline__ ull fadd2(ull a, ull b) {
    ull d; asm("add.rn.f32x2 %0, %1, %2;" : "=l"(d) : "l"(a), "l"(b)); return d;
}

// HW tanh (single MUFU op); validated rel_err ~7e-7 end-to-end
__device__ __forceinline__ float tanh_fast(float x) {
    float y; asm("tanh.approx.f32 %0, %1;" : "=f"(y) : "f"(x)); return y;
}
__device__ __forceinline__ float sig_fast(float x) {
    return fmaf(0.5f, tanh_fast(0.5f * x), 0.5f);
}
__device__ __forceinline__ float sigmoidf_acc(float x) {
    return __fdividef(1.f, 1.f + __expf(-x));
}

#define B_  256
#define S_  1024
#define F_  64
#define H_  64
#define G_  256   // 4*H

// Pair mapping: pair index p -> u = p>>1, s = p&1
//   s=0: columns (u,     u+64 ) = (z_i[u],  z_f[u])
//   s=1: columns (u+128, u+192) = (z_c[u],  z_o[u])
// Column c -> (u = c&63, s = c>>7, half = (c>>6)&1), p = 2u+s.
// xz scratch: [t][b][p] packed float2 (col c0, col c1). 268MB.
__device__ ull   g_xz[(size_t)S_ * B_ * 128];
// h scratch: [b][t][u] floats. 64MB.
__device__ float g_h[(size_t)B_ * S_ * H_];

// =====================================================================
// Kernel A: xz = x @ kernel + bias — REGISTER-DIET version.
// One column per thread (k-packed weights: 64 regs), 2 CTAs/SM.
// 2048 CTAs x 256 thr; each CTA 128 rows, one row per iteration.
// 4-slot shared x ring, depth-3 prefetch, one barrier per iter.
// =====================================================================
__global__ void __launch_bounds__(256, 2) lstm_xgemm(
    const float* __restrict__ x, const float* __restrict__ kern,
    const float* __restrict__ bias)
{
    const int tid = threadIdx.x;
    const int c   = tid;                 // gate column 0..255
    const int u    = c & 63;
    const int s    = (c >> 7) & 1;
    const int half = (c >> 6) & 1;
    const int p    = (u << 1) | s;       // pair index in g_xz layout

    // weights packed along k: wk[m] = (kern[2m][c], kern[2m+1][c])
    ull wk[32];
#pragma unroll
    for (int m = 0; m < 32; m++)
        wk[m] = pack2(kern[(2 * m) * G_ + c], kern[(2 * m + 1) * G_ + c]);
    const float bc = bias[c];

    __shared__ __align__(16) ull xpk[4][32];   // [slot][kpair] ring

    const int base = blockIdx.x * 128;         // 128 rows per CTA
    float* gz = (float*)g_xz;

    float2 v = make_float2(0.f, 0.f);
    if (tid < 32) {
        float2 t0 = *(const float2*)(x + (size_t)(base + 0) * F_ + 2 * tid);
        xpk[0][tid] = pack2(t0.x, t0.y);
        float2 t1 = *(const float2*)(x + (size_t)(base + 1) * F_ + 2 * tid);
        xpk[1][tid] = pack2(t1.x, t1.y);
        v = *(const float2*)(x + (size_t)(base + 2) * F_ + 2 * tid);
    }
    __syncthreads();

#pragma unroll 4
    for (int i = 0; i < 128; i++) {
        // loader: publish row i+2 (LDG issued >=1 iter ago), prefetch i+3
        if (tid < 32 && i + 2 < 128) {
            xpk[(i + 2) & 3][tid] = pack2(v.x, v.y);
            if (i + 3 < 128)
                v = *(const float2*)(x + (size_t)(base + i + 3) * F_ + 2 * tid);
        }

        const ull* xa = xpk[i & 3];
        ull a0 = 0, a1 = 0, a2 = 0, a3 = 0;
#pragma unroll
        for (int m = 0; m < 32; m += 4) {
            a0 = ffma2(wk[m],     xa[m],     a0);
            a1 = ffma2(wk[m + 1], xa[m + 1], a1);
            a2 = ffma2(wk[m + 2], xa[m + 2], a2);
            a3 = ffma2(wk[m + 3], xa[m + 3], a3);
        }
        const float2 hsum = unpack2(fadd2(fadd2(a0, a1), fadd2(a2, a3)));
        const float z = bc + hsum.x + hsum.y;

        const int n  = base + i;               // n = b*S + t
        const int bb = n >> 10, tt = n & 1023;
        // 256 threads write one contiguous 1KB block (coalesced STG.32)
        gz[(((size_t)tt * B_ + bb) * 128 + p) * 2 + half] = z;
        __syncthreads();
    }
}

// =====================================================================
// Kernel B: LSTM recurrence — round-7 proven version (plain ull LDS).
// 128 CTAs x 256 thr (2 rows/CTA, uniform 1 CTA/SM). Depth-8 z ring,
// one __syncthreads per step, h streamed to g_h.
// =====================================================================
__global__ void __launch_bounds__(256, 1) lstm_recur(
    const float* __restrict__ rec)
{
    const int tid  = threadIdx.x;
    const int p    = tid & 127;
    const int r    = tid >> 7;
    const int u    = p >> 1;
    const int s    = p & 1;
    const int brow = blockIdx.x * 2 + r;
    const int c0   = u + (s ? 128 : 0);
    const int c1   = c0 + 64;

    ull wA[32], wB[32];
#pragma unroll
    for (int m = 0; m < 32; m++) {
        wA[m] = pack2(rec[(2 * m) * G_ + c0], rec[(2 * m + 1) * G_ + c0]);
        wB[m] = pack2(rec[(2 * m) * G_ + c1], rec[(2 * m + 1) * G_ + c1]);
    }

    __shared__ __align__(16) ull hpk[2][2][32];   // [parity][row][m] = (h_2m, h_2m+1)

    if (tid < 64) hpk[1][tid >> 5][tid & 31] = 0ull;   // h(-1) = 0 at parity 1

    float c = 0.f;
    const size_t ZS = (size_t)B_ * 128;
    const ull* zp = g_xz + (size_t)brow * 128 + p;
    float* hout = g_h + (size_t)brow * S_ * H_ + u;    // [t][u] stream

    // depth-8 z prefetch ring
    ull zr[8];
#pragma unroll
    for (int d = 0; d < 8; d++) zr[d] = zp[(size_t)d * ZS];
    zp += 8 * ZS;
    __syncthreads();

#pragma unroll 8
    for (int t = 0; t < S_; t++) {
        const int  pr = (t & 1) ^ 1;            // parity holding h(t-1)
        const ull* hp = hpk[pr][r];

        const ull zcur = zr[t & 7];             // z issued 8 steps ago
        if (t + 8 < S_) zr[t & 7] = *zp;
        zp += ZS;

        // matvec: 32 broadcast LDS + 64 FFMA2, 8 chains
        ull a0 = 0, a1 = 0, a2 = 0, a3 = 0;
        ull b0 = 0, b1 = 0, b2 = 0, b3 = 0;
#pragma unroll
        for (int m = 0; m < 32; m += 4) {
            const ull h0 = hp[m],     h1 = hp[m + 1];
            const ull h2 = hp[m + 2], h3 = hp[m + 3];
            a0 = ffma2(wA[m],     h0, a0);
            a1 = ffma2(wA[m + 1], h1, a1);
            a2 = ffma2(wB[m],     h0, a2);
            a3 = ffma2(wB[m + 1], h1, a3);
            b0 = ffma2(wA[m + 2], h2, b0);
            b1 = ffma2(wA[m + 3], h3, b1);
            b2 = ffma2(wB[m + 2], h2, b2);
            b3 = ffma2(wB[m + 3], h3, b3);
        }
        const float2 sa  = unpack2(fadd2(fadd2(a0, a1), fadd2(b0, b1)));
        const float2 sb  = unpack2(fadd2(fadd2(a2, a3), fadd2(b2, b3)));
        const float2 zin = unpack2(zcur);
        const float zv0 = zin.x + sa.x + sa.y;  // z_i (s=0) / z_c (s=1)
        const float zv1 = zin.y + sb.x + sb.y;  // z_f (s=0) / z_o (s=1)

        // own activations, then in-warp exchange with partner lane
        const float g0 = s ? tanh_fast(zv0) : sig_fast(zv0);
        const float g1 = sig_fast(zv1);
        const float t0 = __shfl_xor_sync(0xffffffffu, g0, 1);
        const float t1 = __shfl_xor_sync(0xffffffffu, g1, 1);

        if (s == 0) {                           // lane holds (i,f); partner sent (tc,o)
            c = fmaf(g1, c, g0 * t0);
            const float h = t1 * tanh_fast(c);
            ((float*)hpk[t & 1][r])[u] = h;     // publish h_u(t) for next step
            hout[(size_t)t * H_] = h;           // stream to gmem (off-chain STG)
        }
        __syncthreads();                        // plain BAR (floor ~7)
    }
}

// =====================================================================
// Kernel C: dense head  out[b,t] = sigmoid(h[b,t,:]·dw + db)
// One warp per output, coalesced float2 loads, shfl reduce.
// =====================================================================
__global__ void __launch_bounds__(256, 4) lstm_head(
    const float* __restrict__ dw, const float* __restrict__ db,
    float* __restrict__ out)
{
    const int lane = threadIdx.x & 31;
    const int o    = blockIdx.x * 8 + (threadIdx.x >> 5);   // output index b*S+t

    const float2 hv = *(const float2*)(g_h + (size_t)o * H_ + 2 * lane);
    const float2 wv = *(const float2*)(dw + 2 * lane);
    float pd = hv.x * wv.x + hv.y * wv.y;
#pragma unroll
    for (int off = 16; off; off >>= 1)
        pd += __shfl_xor_sync(0xffffffffu, pd, off);
    if (lane == 0)
        out[o] = sigmoidf_acc(pd + db[0]);
}

// =====================================================================
extern "C" void kernel_launch(void* const* d_in, const int* in_sizes, int n_in,
                              void* d_out, int out_size)
{
    const float* x    = (const float*)d_in[0];  // [256,1024,64]
    const float* kern = (const float*)d_in[1];  // [64,256]
    const float* rec  = (const float*)d_in[2];  // [64,256]
    const float* bias = (const float*)d_in[3];  // [256]
    const float* dw   = (const float*)d_in[4];  // [64,1]
    const float* db   = (const float*)d_in[5];  // [1]
    float* out = (float*)d_out;                 // [256,1024,1]

    lstm_xgemm<<<2048, 256>>>(x, kern, bias);
    lstm_recur<<<128, 256>>>(rec);
    lstm_head<<<(B_ * S_) / 8, 256>>>(dw, db, out);
}

// round 11
// speedup vs baseline: 1.0647x; 1.0647x over previous
#include <cuda_runtime.h>

typedef unsigned long long ull;

// ---------------- packed f32x2 helpers (Blackwell FFMA2 path) ----------------
__device__ __forceinline__ ull pack2(float a, float b) {
    ull r; asm("mov.b64 %0, {%1,%2};" : "=l"(r) : "f"(a), "f"(b)); return r;
}
__device__ __forceinline__ float2 unpack2(ull v) {
    float2 f; asm("mov.b64 {%0,%1}, %2;" : "=f"(f.x), "=f"(f.y) : "l"(v)); return f;
}
__device__ __forceinline__ ull ffma2(ull a, ull b, ull c) {
    ull d; asm("fma.rn.f32x2 %0, %1, %2, %3;" : "=l"(d) : "l"(a), "l"(b), "l"(c)); return d;
}
__device__ __forceinline__ ull fadd2(ull a, ull b) {
    ull d; asm("add.rn.f32x2 %0, %1, %2;" : "=l"(d) : "l"(a), "l"(b)); return d;
}

// HW tanh (single MUFU op); validated rel_err ~7e-7 end-to-end
__device__ __forceinline__ float tanh_fast(float x) {
    float y; asm("tanh.approx.f32 %0, %1;" : "=f"(y) : "f"(x)); return y;
}
__device__ __forceinline__ float sig_fast(float x) {
    return fmaf(0.5f, tanh_fast(0.5f * x), 0.5f);
}
__device__ __forceinline__ float sigmoidf_acc(float x) {
    return __fdividef(1.f, 1.f + __expf(-x));
}

#define B_  256
#define S_  1024
#define F_  64
#define H_  64
#define G_  256   // 4*H

// g_xz ull slot q of a row holds floats (fi=2q, fi=2q+1) where
//   fi -> column c: u = fi>>2, s = (fi>>1)&1, half = fi&1,
//   c = (s?128:0) + 64*half + u.
// Recur thread p reads slot p = 2u+s -> (z_{c0}, z_{c1}), c0=u+(s?128:0), c1=c0+64.
__device__ ull   g_xz[(size_t)S_ * B_ * 128];
// h scratch: [b][t][u] floats. 64MB.
__device__ float g_h[(size_t)B_ * S_ * H_];

// =====================================================================
// Kernel A: xz = x @ kernel + bias — WARP-AUTONOMOUS (no block barriers).
// 1024 CTAs x 256 thr. Warp w: col-block cb=w&3 (64 cols), stripe=w>>2;
// handles 128 rows independently. Per row: lane loads x float2 (coalesced),
// warp-private smem ring + __syncwarp broadcast, 64 FFMA2, 1 STG.64.
// =====================================================================
__global__ void __launch_bounds__(256, 1) lstm_xgemm(
    const float* __restrict__ x, const float* __restrict__ kern,
    const float* __restrict__ bias)
{
    const int tid    = threadIdx.x;
    const int lane   = tid & 31;
    const int w      = tid >> 5;
    const int cb     = w & 3;          // column block (64 cols)
    const int stripe = w >> 2;         // row stripe (0/1)

    // lane's ull output slot within the row's 128-slot chunk
    const int q    = cb * 32 + lane;
    const int u    = q >> 1;
    const int s    = q & 1;
    const int cLo  = (s ? 128 : 0) + u;        // half=0 column
    const int cHi  = cLo + 64;                 // half=1 column

    // k-packed weights for the two columns: 64 ull = 128 regs
    ull wLo[32], wHi[32];
#pragma unroll
    for (int m = 0; m < 32; m++) {
        wLo[m] = pack2(kern[(2 * m) * G_ + cLo], kern[(2 * m + 1) * G_ + cLo]);
        wHi[m] = pack2(kern[(2 * m) * G_ + cHi], kern[(2 * m + 1) * G_ + cHi]);
    }
    const float bLo = bias[cLo], bHi = bias[cHi];

    __shared__ __align__(16) ull xbuf[8][4][32];   // warp-private 4-slot rings

    const int rowbase = blockIdx.x * 256 + stripe * 128;   // 128 rows per warp
    const float* xp = x + (size_t)rowbase * F_ + 2 * lane;

    // ring prologue: slots 0,1 filled; v0,v1 in flight for rows 2,3
    {
        float2 t0 = *(const float2*)(xp);            // row +0
        xbuf[w][0][lane] = pack2(t0.x, t0.y);
        float2 t1 = *(const float2*)(xp + F_);       // row +1
        xbuf[w][1][lane] = pack2(t1.x, t1.y);
    }
    float2 v0 = *(const float2*)(xp + 2 * F_);       // row +2
    float2 v1 = *(const float2*)(xp + 3 * F_);       // row +3
    xp += 4 * F_;
    __syncwarp();

#pragma unroll 4
    for (int i = 0; i < 128; i++) {
        // publish row i+2 (LDG'd 2 iters ago), start LDG for row i+4
        if (i + 2 < 128) {
            xbuf[w][(i + 2) & 3][lane] = pack2(v0.x, v0.y);
            v0 = v1;
            if (i + 4 < 128) { v1 = *(const float2*)xp; xp += F_; }
        }

        const ull* xb = xbuf[w][i & 3];
        ull a0 = 0, a1 = 0, a2 = 0, a3 = 0;
#pragma unroll
        for (int m = 0; m < 32; m += 2) {
            const ull x0 = xb[m], x1 = xb[m + 1];
            a0 = ffma2(wLo[m],     x0, a0);
            a1 = ffma2(wLo[m + 1], x1, a1);
            a2 = ffma2(wHi[m],     x0, a2);
            a3 = ffma2(wHi[m + 1], x1, a3);
        }
        const float2 sLo = unpack2(fadd2(a0, a1));
        const float2 sHi = unpack2(fadd2(a2, a3));
        const float zLo = bLo + sLo.x + sLo.y;
        const float zHi = bHi + sHi.x + sHi.y;

        const int n  = rowbase + i;                 // n = b*S + t
        const int bb = n >> 10, tt = n & 1023;
        g_xz[((size_t)tt * B_ + bb) * 128 + q] = pack2(zLo, zHi);  // STG.64 coalesced

        __syncwarp();    // warp-local; orders ring writes vs next iter's reads
    }
}

// =====================================================================
// Kernel B: LSTM recurrence — round-7 proven version VERBATIM
// (named bar per row, plain ull LDS, depth-8 z ring, 8 FFMA2 chains).
// 128 CTAs x 256 thr (2 rows/CTA, uniform 1 CTA/SM). h -> g_h.
// =====================================================================
__global__ void __launch_bounds__(256, 1) lstm_recur(
    const float* __restrict__ rec)
{
    const int tid  = threadIdx.x;
    const int p    = tid & 127;
    const int r    = tid >> 7;
    const int u    = p >> 1;
    const int s    = p & 1;
    const int brow = blockIdx.x * 2 + r;
    const int c0   = u + (s ? 128 : 0);
    const int c1   = c0 + 64;

    ull wA[32], wB[32];
#pragma unroll
    for (int m = 0; m < 32; m++) {
        wA[m] = pack2(rec[(2 * m) * G_ + c0], rec[(2 * m + 1) * G_ + c0]);
        wB[m] = pack2(rec[(2 * m) * G_ + c1], rec[(2 * m + 1) * G_ + c1]);
    }

    __shared__ __align__(16) ull hpk[2][2][32];   // [parity][row][m] = (h_2m, h_2m+1)

    if (tid < 64) hpk[1][tid >> 5][tid & 31] = 0ull;   // h(-1) = 0 at parity 1

    float c = 0.f;
    const size_t ZS = (size_t)B_ * 128;
    const ull* zp = g_xz + (size_t)brow * 128 + p;
    float* hout = g_h + (size_t)brow * S_ * H_ + u;    // [t][u] stream

    // depth-8 z prefetch ring
    ull zr[8];
#pragma unroll
    for (int d = 0; d < 8; d++) zr[d] = zp[(size_t)d * ZS];
    zp += 8 * ZS;
    __syncthreads();

    const int barid = r + 1;     // named barrier per row (128 threads each)

#pragma unroll 8
    for (int t = 0; t < S_; t++) {
        const int  pr = (t & 1) ^ 1;            // parity holding h(t-1)
        const ull* hp = hpk[pr][r];

        const ull zcur = zr[t & 7];             // z issued 8 steps ago
        if (t + 8 < S_) zr[t & 7] = *zp;
        zp += ZS;

        // matvec: 32 broadcast LDS + 64 FFMA2, 8 chains
        ull a0 = 0, a1 = 0, a2 = 0, a3 = 0;
        ull b0 = 0, b1 = 0, b2 = 0, b3 = 0;
#pragma unroll
        for (int m = 0; m < 32; m += 4) {
            const ull h0 = hp[m],     h1 = hp[m + 1];
            const ull h2 = hp[m + 2], h3 = hp[m + 3];
            a0 = ffma2(wA[m],     h0, a0);
            a1 = ffma2(wA[m + 1], h1, a1);
            a2 = ffma2(wB[m],     h0, a2);
            a3 = ffma2(wB[m + 1], h1, a3);
            b0 = ffma2(wA[m + 2], h2, b0);
            b1 = ffma2(wA[m + 3], h3, b1);
            b2 = ffma2(wB[m + 2], h2, b2);
            b3 = ffma2(wB[m + 3], h3, b3);
        }
        const float2 sa  = unpack2(fadd2(fadd2(a0, a1), fadd2(b0, b1)));
        const float2 sb  = unpack2(fadd2(fadd2(a2, a3), fadd2(b2, b3)));
        const float2 zin = unpack2(zcur);
        const float zv0 = zin.x + sa.x + sa.y;  // z_i (s=0) / z_c (s=1)
        const float zv1 = zin.y + sb.x + sb.y;  // z_f (s=0) / z_o (s=1)

        // own activations, then in-warp exchange with partner lane
        const float g0 = s ? tanh_fast(zv0) : sig_fast(zv0);
        const float g1 = sig_fast(zv1);
        const float t0 = __shfl_xor_sync(0xffffffffu, g0, 1);
        const float t1 = __shfl_xor_sync(0xffffffffu, g1, 1);

        if (s == 0) {                           // lane holds (i,f); partner sent (tc,o)
            c = fmaf(g1, c, g0 * t0);
            const float h = t1 * tanh_fast(c);
            ((float*)hpk[t & 1][r])[u] = h;     // publish h_u(t) for next step
            hout[(size_t)t * H_] = h;           // stream to gmem (off-chain STG)
        }
        asm volatile("bar.sync %0, 128;" :: "r"(barid) : "memory");
    }
}

// =====================================================================
// Kernel C: dense head  out[b,t] = sigmoid(h[b,t,:]·dw + db)
// One warp per output, coalesced float2 loads, shfl reduce.
// =====================================================================
__global__ void __launch_bounds__(256, 4) lstm_head(
    const float* __restrict__ dw, const float* __restrict__ db,
    float* __restrict__ out)
{
    const int lane = threadIdx.x & 31;
    const int o    = blockIdx.x * 8 + (threadIdx.x >> 5);   // output index b*S+t

    const float2 hv = *(const float2*)(g_h + (size_t)o * H_ + 2 * lane);
    const float2 wv = *(const float2*)(dw + 2 * lane);
    float pd = hv.x * wv.x + hv.y * wv.y;
#pragma unroll
    for (int off = 16; off; off >>= 1)
        pd += __shfl_xor_sync(0xffffffffu, pd, off);
    if (lane == 0)
        out[o] = sigmoidf_acc(pd + db[0]);
}

// =====================================================================
extern "C" void kernel_launch(void* const* d_in, const int* in_sizes, int n_in,
                              void* d_out, int out_size)
{
    const float* x    = (const float*)d_in[0];  // [256,1024,64]
    const float* kern = (const float*)d_in[1];  // [64,256]
    const float* rec  = (const float*)d_in[2];  // [64,256]
    const float* bias = (const float*)d_in[3];  // [256]
    const float* dw   = (const float*)d_in[4];  // [64,1]
    const float* db   = (const float*)d_in[5];  // [1]
    float* out = (float*)d_out;                 // [256,1024,1]

    lstm_xgemm<<<1024, 256>>>(x, kern, bias);
    lstm_recur<<<128, 256>>>(rec);
    lstm_head<<<(B_ * S_) / 8, 256>>>(dw, db, out);
}

// round 12
// speedup vs baseline: 1.2720x; 1.1947x over previous
#include <cuda_runtime.h>

typedef unsigned long long ull;

// ---------------- packed f32x2 helpers (Blackwell FFMA2 path) ----------------
__device__ __forceinline__ ull pack2(float a, float b) {
    ull r; asm("mov.b64 %0, {%1,%2};" : "=l"(r) : "f"(a), "f"(b)); return r;
}
__device__ __forceinline__ float2 unpack2(ull v) {
    float2 f; asm("mov.b64 {%0,%1}, %2;" : "=f"(f.x), "=f"(f.y) : "l"(v)); return f;
}
__device__ __forceinline__ ull ffma2(ull a, ull b, ull c) {
    ull d; asm("fma.rn.f32x2 %0, %1, %2, %3;" : "=l"(d) : "l"(a), "l"(b), "l"(c)); return d;
}
__device__ __forceinline__ ull fadd2(ull a, ull b) {
    ull d; asm("add.rn.f32x2 %0, %1, %2;" : "=l"(d) : "l"(a), "l"(b)); return d;
}

// HW tanh (single MUFU op); validated rel_err ~7e-7 end-to-end
__device__ __forceinline__ float tanh_fast(float x) {
    float y; asm("tanh.approx.f32 %0, %1;" : "=f"(y) : "f"(x)); return y;
}
__device__ __forceinline__ float sig_fast(float x) {
    return fmaf(0.5f, tanh_fast(0.5f * x), 0.5f);
}
__device__ __forceinline__ float sigmoidf_acc(float x) {
    return __fdividef(1.f, 1.f + __expf(-x));
}

#define B_  256
#define S_  1024
#define F_  64
#define H_  64
#define G_  256   // 4*H

// Pair mapping: pair index p -> u = p>>1, s = p&1
//   s=0: columns (u,     u+64 ) = (z_i[u],  z_f[u])
//   s=1: columns (u+128, u+192) = (z_c[u],  z_o[u])
// xz scratch: [t][b][p] packed float2 (col c0, col c1). 268MB.
__device__ ull   g_xz[(size_t)S_ * B_ * 128];
// h scratch: [b][t][u] floats. 64MB.
__device__ float g_h[(size_t)B_ * S_ * H_];

// =====================================================================
// Kernel A: xz = x @ kernel + bias — round-7 layout, 8 rows/barrier.
// 1024 CTAs x 256 thr; each CTA 256 rows = 32 iters x 8 rows.
// Thread (j, half): column pair j, rows half*4+{0..3} of the oct.
// 4-slot shared ring (8 rows each), all 256 threads load (1 ull/thread),
// depth-2+ LDG prefetch, ONE barrier per 8 rows.
// =====================================================================
__global__ void __launch_bounds__(256, 1) lstm_xgemm(
    const float* __restrict__ x, const float* __restrict__ kern,
    const float* __restrict__ bias)
{
    const int tid  = threadIdx.x;
    const int j    = tid & 127;
    const int half = tid >> 7;
    const int u    = j >> 1;
    const int s    = j & 1;
    const int c0   = u + (s ? 128 : 0);
    const int c1   = c0 + 64;

    // k-packed weights for own two columns: 64 ull = 128 regs
    ull wA[32], wB[32];
#pragma unroll
    for (int m = 0; m < 32; m++) {
        wA[m] = pack2(kern[(2 * m) * G_ + c0], kern[(2 * m + 1) * G_ + c0]);
        wB[m] = pack2(kern[(2 * m) * G_ + c1], kern[(2 * m + 1) * G_ + c1]);
    }
    const float bc0 = bias[c0], bc1 = bias[c1];

    __shared__ __align__(16) ull xpk[4][8][32];   // [slot][row-in-oct][kpair]

    // loader role: every thread loads one (row, kpair) element per oct
    const int lr = tid >> 5;          // 0..7 row within oct
    const int lm = tid & 31;          // kpair
    const int base = blockIdx.x * 256;     // 256 rows per CTA (32 octs)

    // prologue: fill slots 0,1; v holds oct 2's element
    {
        float2 t0 = *(const float2*)(x + (size_t)(base + 0 * 8 + lr) * F_ + 2 * lm);
        xpk[0][lr][lm] = pack2(t0.x, t0.y);
        float2 t1 = *(const float2*)(x + (size_t)(base + 1 * 8 + lr) * F_ + 2 * lm);
        xpk[1][lr][lm] = pack2(t1.x, t1.y);
    }
    float2 v = *(const float2*)(x + (size_t)(base + 2 * 8 + lr) * F_ + 2 * lm);
    __syncthreads();

    for (int i = 0; i < 32; i++) {
        // publish oct i+2 (LDG'd earlier), start LDG for oct i+3
        if (i + 2 < 32) {
            xpk[(i + 2) & 3][lr][lm] = pack2(v.x, v.y);
            if (i + 3 < 32)
                v = *(const float2*)(x + (size_t)(base + (i + 3) * 8 + lr) * F_ + 2 * lm);
        }

        const ull* xs = xpk[i & 3][half << 2];   // rows half*4 .. half*4+3 (contiguous)
        // 8 accumulator chains: 4 rows x 2 cols
        ull acc[8];
#pragma unroll
        for (int q = 0; q < 8; q++) acc[q] = 0ull;
#pragma unroll
        for (int m = 0; m < 32; m++) {
            const ull x0 = xs[m];           // row 0 of my quad
            const ull x1 = xs[32 + m];      // row 1
            const ull x2 = xs[64 + m];      // row 2
            const ull x3 = xs[96 + m];      // row 3
            acc[0] = ffma2(wA[m], x0, acc[0]);
            acc[1] = ffma2(wB[m], x0, acc[1]);
            acc[2] = ffma2(wA[m], x1, acc[2]);
            acc[3] = ffma2(wB[m], x1, acc[3]);
            acc[4] = ffma2(wA[m], x2, acc[4]);
            acc[5] = ffma2(wB[m], x2, acc[5]);
            acc[6] = ffma2(wA[m], x3, acc[6]);
            acc[7] = ffma2(wB[m], x3, acc[7]);
        }

        const int nbase = base + i * 8 + half * 4;   // first of my 4 rows
#pragma unroll
        for (int rr = 0; rr < 4; rr++) {
            const float2 sc0 = unpack2(acc[2 * rr]);
            const float2 sc1 = unpack2(acc[2 * rr + 1]);
            const ull rz = pack2(bc0 + sc0.x + sc0.y, bc1 + sc1.x + sc1.y);
            const int n  = nbase + rr;              // n = b*S + t
            const int bb = n >> 10, tt = n & 1023;
            g_xz[((size_t)tt * B_ + bb) * 128 + j] = rz;
        }
        __syncthreads();
    }
}

// =====================================================================
// Kernel B: LSTM recurrence — round-7 proven version VERBATIM
// (named bar per row, plain ull LDS, depth-8 z ring, 8 FFMA2 chains).
// 128 CTAs x 256 thr (2 rows/CTA, uniform 1 CTA/SM). h -> g_h.
// =====================================================================
__global__ void __launch_bounds__(256, 1) lstm_recur(
    const float* __restrict__ rec)
{
    const int tid  = threadIdx.x;
    const int p    = tid & 127;
    const int r    = tid >> 7;
    const int u    = p >> 1;
    const int s    = p & 1;
    const int brow = blockIdx.x * 2 + r;
    const int c0   = u + (s ? 128 : 0);
    const int c1   = c0 + 64;

    ull wA[32], wB[32];
#pragma unroll
    for (int m = 0; m < 32; m++) {
        wA[m] = pack2(rec[(2 * m) * G_ + c0], rec[(2 * m + 1) * G_ + c0]);
        wB[m] = pack2(rec[(2 * m) * G_ + c1], rec[(2 * m + 1) * G_ + c1]);
    }

    __shared__ __align__(16) ull hpk[2][2][32];   // [parity][row][m] = (h_2m, h_2m+1)

    if (tid < 64) hpk[1][tid >> 5][tid & 31] = 0ull;   // h(-1) = 0 at parity 1

    float c = 0.f;
    const size_t ZS = (size_t)B_ * 128;
    const ull* zp = g_xz + (size_t)brow * 128 + p;
    float* hout = g_h + (size_t)brow * S_ * H_ + u;    // [t][u] stream

    // depth-8 z prefetch ring
    ull zr[8];
#pragma unroll
    for (int d = 0; d < 8; d++) zr[d] = zp[(size_t)d * ZS];
    zp += 8 * ZS;
    __syncthreads();

    const int barid = r + 1;     // named barrier per row (128 threads each)

#pragma unroll 8
    for (int t = 0; t < S_; t++) {
        const int  pr = (t & 1) ^ 1;            // parity holding h(t-1)
        const ull* hp = hpk[pr][r];

        const ull zcur = zr[t & 7];             // z issued 8 steps ago
        if (t + 8 < S_) zr[t & 7] = *zp;
        zp += ZS;

        // matvec: 32 broadcast LDS + 64 FFMA2, 8 chains
        ull a0 = 0, a1 = 0, a2 = 0, a3 = 0;
        ull b0 = 0, b1 = 0, b2 = 0, b3 = 0;
#pragma unroll
        for (int m = 0; m < 32; m += 4) {
            const ull h0 = hp[m],     h1 = hp[m + 1];
            const ull h2 = hp[m + 2], h3 = hp[m + 3];
            a0 = ffma2(wA[m],     h0, a0);
            a1 = ffma2(wA[m + 1], h1, a1);
            a2 = ffma2(wB[m],     h0, a2);
            a3 = ffma2(wB[m + 1], h1, a3);
            b0 = ffma2(wA[m + 2], h2, b0);
            b1 = ffma2(wA[m + 3], h3, b1);
            b2 = ffma2(wB[m + 2], h2, b2);
            b3 = ffma2(wB[m + 3], h3, b3);
        }
        const float2 sa  = unpack2(fadd2(fadd2(a0, a1), fadd2(b0, b1)));
        const float2 sb  = unpack2(fadd2(fadd2(a2, a3), fadd2(b2, b3)));
        const float2 zin = unpack2(zcur);
        const float zv0 = zin.x + sa.x + sa.y;  // z_i (s=0) / z_c (s=1)
        const float zv1 = zin.y + sb.x + sb.y;  // z_f (s=0) / z_o (s=1)

        // own activations, then in-warp exchange with partner lane
        const float g0 = s ? tanh_fast(zv0) : sig_fast(zv0);
        const float g1 = sig_fast(zv1);
        const float t0 = __shfl_xor_sync(0xffffffffu, g0, 1);
        const float t1 = __shfl_xor_sync(0xffffffffu, g1, 1);

        if (s == 0) {                           // lane holds (i,f); partner sent (tc,o)
            c = fmaf(g1, c, g0 * t0);
            const float h = t1 * tanh_fast(c);
            ((float*)hpk[t & 1][r])[u] = h;     // publish h_u(t) for next step
            hout[(size_t)t * H_] = h;           // stream to gmem (off-chain STG)
        }
        asm volatile("bar.sync %0, 128;" :: "r"(barid) : "memory");
    }
}

// =====================================================================
// Kernel C: dense head  out[b,t] = sigmoid(h[b,t,:]·dw + db)
// One warp per output, coalesced float2 loads, shfl reduce.
// =====================================================================
__global__ void __launch_bounds__(256, 4) lstm_head(
    const float* __restrict__ dw, const float* __restrict__ db,
    float* __restrict__ out)
{
    const int lane = threadIdx.x & 31;
    const int o    = blockIdx.x * 8 + (threadIdx.x >> 5);   // output index b*S+t

    const float2 hv = *(const float2*)(g_h + (size_t)o * H_ + 2 * lane);
    const float2 wv = *(const float2*)(dw + 2 * lane);
    float pd = hv.x * wv.x + hv.y * wv.y;
#pragma unroll
    for (int off = 16; off; off >>= 1)
        pd += __shfl_xor_sync(0xffffffffu, pd, off);
    if (lane == 0)
        out[o] = sigmoidf_acc(pd + db[0]);
}

// =====================================================================
extern "C" void kernel_launch(void* const* d_in, const int* in_sizes, int n_in,
                              void* d_out, int out_size)
{
    const float* x    = (const float*)d_in[0];  // [256,1024,64]
    const float* kern = (const float*)d_in[1];  // [64,256]
    const float* rec  = (const float*)d_in[2];  // [64,256]
    const float* bias = (const float*)d_in[3];  // [256]
    const float* dw   = (const float*)d_in[4];  // [64,1]
    const float* db   = (const float*)d_in[5];  // [1]
    float* out = (float*)d_out;                 // [256,1024,1]

    lstm_xgemm<<<1024, 256>>>(x, kern, bias);
    lstm_recur<<<128, 256>>>(rec);
    lstm_head<<<(B_ * S_) / 8, 256>>>(dw, db, out);
}